// round 2
// baseline (speedup 1.0000x reference)
#include <cuda_runtime.h>
#include <cuda_bf16.h>

#define NN    50000
#define INDIM 128
#define HEADS 8
#define RDIM  16
#define DDIM  16

// Scratch (no cudaMalloc allowed): K, Q, V projections + z accumulator
__device__ float g_K[NN * 128];
__device__ float g_Q[NN * 128];
__device__ float g_V[NN * 128];
__device__ float g_z[NN * HEADS];

// ---------------------------------------------------------------------------
// Zero-init d_out (wV accumulator) and g_z
// ---------------------------------------------------------------------------
__global__ void zero_kernel(float4* __restrict__ out) {
    int i = blockIdx.x * blockDim.x + threadIdx.x;
    if (i < NN * 32) out[i] = make_float4(0.f, 0.f, 0.f, 0.f);
    if (i < NN * 2)  ((float4*)g_z)[i] = make_float4(0.f, 0.f, 0.f, 0.f);
}

// ---------------------------------------------------------------------------
// Fused K/Q/V projection GEMM: C = h @ W, one weight matrix per blockIdx.y
// BM=128, BN=128 (full weight width), BK=8, 256 threads, 8x8 per-thread tile
// ---------------------------------------------------------------------------
__global__ __launch_bounds__(256, 2)
void kqv_gemm(const float* __restrict__ h,
              const float* __restrict__ wq,   // K = h @ q
              const float* __restrict__ wp,   // Q = h @ p
              const float* __restrict__ wv) { // V = h @ Wv
    __shared__ float as[8][128];   // A^T tile: as[k][m]
    __shared__ float bs[8][128];   // B tile:   bs[k][n]

    const float* w;
    float* outp;
    if (blockIdx.y == 0)      { w = wq; outp = g_K; }
    else if (blockIdx.y == 1) { w = wp; outp = g_Q; }
    else                      { w = wv; outp = g_V; }

    const int m0  = blockIdx.x * 128;
    const int tid = threadIdx.x;
    const int ty  = tid >> 4;    // 0..15 -> m group
    const int tx  = tid & 15;    // 0..15 -> n group

    // A-load mapping: 128 rows x 8 k per tile
    const int lm = tid >> 1;          // row within tile 0..127
    const int lk = (tid & 1) * 4;     // k offset 0 or 4
    // B-load mapping: 8 k-rows x 128 n
    const int bk = tid >> 5;          // 0..7
    const int bn = (tid & 31) * 4;    // 0..124

    float acc[8][8];
#pragma unroll
    for (int i = 0; i < 8; i++)
#pragma unroll
        for (int j = 0; j < 8; j++) acc[i][j] = 0.f;

    for (int k0 = 0; k0 < 128; k0 += 8) {
        // Load A tile (transposed into smem), guard tail rows
        float4 av = make_float4(0.f, 0.f, 0.f, 0.f);
        int row = m0 + lm;
        if (row < NN) av = *(const float4*)&h[row * 128 + k0 + lk];
        as[lk + 0][lm] = av.x;
        as[lk + 1][lm] = av.y;
        as[lk + 2][lm] = av.z;
        as[lk + 3][lm] = av.w;
        // Load B tile
        *(float4*)&bs[bk][bn] = *(const float4*)&w[(k0 + bk) * 128 + bn];
        __syncthreads();

#pragma unroll
        for (int k = 0; k < 8; k++) {
            float a[8], b[8];
            *(float4*)(a)     = *(const float4*)&as[k][ty * 8];
            *(float4*)(a + 4) = *(const float4*)&as[k][ty * 8 + 4];
            *(float4*)(b)     = *(const float4*)&bs[k][tx * 8];
            *(float4*)(b + 4) = *(const float4*)&bs[k][tx * 8 + 4];
#pragma unroll
            for (int i = 0; i < 8; i++)
#pragma unroll
                for (int j = 0; j < 8; j++)
                    acc[i][j] = fmaf(a[i], b[j], acc[i][j]);
        }
        __syncthreads();
    }

#pragma unroll
    for (int i = 0; i < 8; i++) {
        int row = m0 + ty * 8 + i;
        if (row < NN) {
            *(float4*)&outp[row * 128 + tx * 8]     =
                make_float4(acc[i][0], acc[i][1], acc[i][2], acc[i][3]);
            *(float4*)&outp[row * 128 + tx * 8 + 4] =
                make_float4(acc[i][4], acc[i][5], acc[i][6], acc[i][7]);
        }
    }
}

// ---------------------------------------------------------------------------
// Edge kernel: one warp per edge (grid-stride).
// lane t: head = t>>2, covers floats [4t, 4t+4) of the 128-float node row.
// ---------------------------------------------------------------------------
__global__ void edge_kernel(const int* __restrict__ src,
                            const int* __restrict__ dst,
                            float* __restrict__ out,
                            int E) {
    const int lane    = threadIdx.x & 31;
    const int warpId  = (blockIdx.x * blockDim.x + threadIdx.x) >> 5;
    const int nwarps  = (gridDim.x * blockDim.x) >> 5;
    const float4* __restrict__ K4 = (const float4*)g_K;
    const float4* __restrict__ Q4 = (const float4*)g_Q;
    const float4* __restrict__ V4 = (const float4*)g_V;
    const int head = lane >> 2;

    for (int e = warpId; e < E; e += nwarps) {
        const int s = __ldg(&src[e]);   // warp-uniform broadcast load
        const int d = __ldg(&dst[e]);

        float4 kv = K4[s * 32 + lane];
        float4 qv = Q4[d * 32 + lane];
        float ps = kv.x * qv.x + kv.y * qv.y + kv.z * qv.z + kv.w * qv.w;
        ps += __shfl_xor_sync(0xFFFFFFFFu, ps, 1);
        ps += __shfl_xor_sync(0xFFFFFFFFu, ps, 2);
        // score = exp(clip(dot / 4, -5, 5))
        float sc = __expf(fminf(fmaxf(ps * 0.25f, -5.f), 5.f));

        float4 vv = V4[s * 32 + lane];
        float rx = vv.x * sc, ry = vv.y * sc, rz = vv.z * sc, rw = vv.w * sc;
        float* addr = out + d * 128 + lane * 4;
        asm volatile("red.global.add.v4.f32 [%0], {%1, %2, %3, %4};"
                     :: "l"(addr), "f"(rx), "f"(ry), "f"(rz), "f"(rw)
                     : "memory");
        if ((lane & 3) == 0) atomicAdd(&g_z[d * HEADS + head], sc);
    }
}

// ---------------------------------------------------------------------------
// Finalize: out = wV / z, z==0 -> 0.001
// ---------------------------------------------------------------------------
__global__ void finalize_kernel(float4* __restrict__ out) {
    int i = blockIdx.x * blockDim.x + threadIdx.x;   // over NN*32 float4s
    if (i < NN * 32) {
        int n    = i >> 5;
        int head = (i >> 2) & 7;
        float zz = g_z[n * HEADS + head];
        zz = (zz == 0.f) ? 0.001f : zz;
        float inv = 1.0f / zz;
        float4 v = out[i];
        v.x *= inv; v.y *= inv; v.z *= inv; v.w *= inv;
        out[i] = v;
    }
}

extern "C" void kernel_launch(void* const* d_in, const int* in_sizes, int n_in,
                              void* d_out, int out_size) {
    const float* h   = (const float*)d_in[0];
    const int*   src = (const int*)d_in[1];
    const int*   dst = (const int*)d_in[2];
    const float* p   = (const float*)d_in[3];
    const float* q   = (const float*)d_in[4];
    const float* wv  = (const float*)d_in[5];
    float* out = (float*)d_out;
    const int E = in_sizes[1];

    zero_kernel<<<(NN * 32 + 255) / 256, 256>>>((float4*)out);

    dim3 ggrid((NN + 127) / 128, 3);
    kqv_gemm<<<ggrid, 256>>>(h, q, p, wv);

    edge_kernel<<<4096, 256>>>(src, dst, out, E);

    finalize_kernel<<<(NN * 32 + 255) / 256, 256>>>((float4*)out);
}